// round 2
// baseline (speedup 1.0000x reference)
#include <cuda_runtime.h>

#define N_NODES 50000
#define N_EDGES 800000
#define D 64
#define GRID 128
#define TPB 256

// ---------------- scratch (static device globals; no allocation) ----------------
__device__ float g_deg[N_NODES];
__device__ float g_agg0[N_NODES * D];
__device__ float g_agg1[N_NODES * D];
__device__ float g_h[N_NODES * D];

// barrier state: monotonic, never reset (safe across graph replays)
__device__ unsigned g_cnt = 0;
__device__ unsigned g_gen = 0;

// ---------------- helpers ----------------
__device__ __forceinline__ void red_add_v4(float* p, float4 v) {
    asm volatile("red.global.add.v4.f32 [%0], {%1,%2,%3,%4};"
                 :: "l"(p), "f"(v.x), "f"(v.y), "f"(v.z), "f"(v.w) : "memory");
}
__device__ __forceinline__ void red_add_f32(float* p, float v) {
    asm volatile("red.global.add.f32 [%0], %1;" :: "l"(p), "f"(v) : "memory");
}

// software grid barrier (all GRID blocks co-resident; monotonic counters)
__device__ __forceinline__ void grid_bar() {
    __syncthreads();
    if (threadIdx.x == 0) {
        __threadfence();
        unsigned my = atomicAdd(&g_cnt, 1u) + 1u;
        unsigned need = (my + GRID - 1u) / GRID;      // barrier round of this arrival
        if ((my % GRID) == 0u) atomicAdd(&g_gen, 1u); // last arrival releases round
        while (*((volatile unsigned*)&g_gen) < need) {}
        __threadfence();
    }
    __syncthreads();
}

// ---------------- fused persistent kernel ----------------
__global__ void __launch_bounds__(TPB)
sage_fused_kernel(const float* __restrict__ x,
                  const void* __restrict__ srcp,
                  const void* __restrict__ dstp,
                  const float* __restrict__ W_self0, const float* __restrict__ W_neigh0,
                  const float* __restrict__ b0,
                  const float* __restrict__ W_self1, const float* __restrict__ W_neigh1,
                  const float* __restrict__ b1,
                  float* __restrict__ outp) {
    const int tid = threadIdx.x;
    const int bid = blockIdx.x;
    const int gtid = bid * TPB + tid;
    const int gstride = GRID * TPB;

    __shared__ float Wsm[D * D];     // 16 KB
    __shared__ float At[D][65];      // ~16.6 KB
    __shared__ float invs[D];
    __shared__ int s_any;

    // ---- index dtype detection (every block computes identically; no comm needed) ----
    if (tid == 0) s_any = 0;
    __syncthreads();
    {
        int any = 0;
        const int* si = (const int*)srcp;
        for (int i = tid; i < 2048; i += TPB) any |= si[2 * i + 1];
        if (any) atomicOr(&s_any, 1);
    }
    __syncthreads();
    const bool is64 = (s_any == 0);  // high words all zero -> int64 little-endian

    // ---- phase A: zero scratch ----
    {
        float4 z = make_float4(0.f, 0.f, 0.f, 0.f);
        float4* pd = (float4*)g_deg;
        for (int j = gtid; j < N_NODES / 4; j += gstride) pd[j] = z;
        float4* p0 = (float4*)g_agg0;
        float4* p1 = (float4*)g_agg1;
        for (int j = gtid; j < N_NODES * D / 4; j += gstride) { p0[j] = z; p1[j] = z; }
    }
    grid_bar();

    // ---- phase B: scatter layer 0 (+degree) ----
    for (int e = gtid; e < N_EDGES; e += gstride) {
        int s, dn;
        if (is64) {
            s  = (int)((const long long*)srcp)[e];
            dn = (int)((const long long*)dstp)[e];
        } else {
            s  = ((const int*)srcp)[e];
            dn = ((const int*)dstp)[e];
        }
        red_add_f32(&g_deg[dn], 1.0f);
        const float4* fs = (const float4*)(x + (long long)s * D);
        float* op = g_agg0 + (long long)dn * D;
#pragma unroll
        for (int j = 0; j < 16; j++) red_add_v4(op + j * 4, __ldg(fs + j));
    }
    grid_bar();

    // ---- GEMM phase macro: out = [relu](in@Wself + (agg*inv)@Wneigh + b) ----
    const int tc = tid & 15;    // col group: cols 4*tc..4*tc+3
    const int tr = tid >> 4;    // 0..15 : rows tr*4..tr*4+3
#define SAGE_LAYER(IN, AGG, WSELF, WNEIGH, BIAS, OUT, RELU)                              \
    for (int t = bid; t < (N_NODES + D - 1) / D; t += GRID) {                            \
        const int row0 = t * D;                                                          \
        float acc[4][4];                                                                 \
        _Pragma("unroll") for (int i = 0; i < 4; i++)                                    \
            _Pragma("unroll") for (int j = 0; j < 4; j++) acc[i][j] = 0.f;               \
        if (tid < D) {                                                                   \
            int r = row0 + tid;                                                          \
            float dg = (r < N_NODES) ? g_deg[r] : 1.0f;                                  \
            invs[tid] = 1.0f / fmaxf(dg, 1.0f);                                          \
        }                                                                                \
        _Pragma("unroll 2") for (int pass = 0; pass < 2; pass++) {                       \
            const float* W  = pass ? (WNEIGH) : (WSELF);                                 \
            const float* SP = pass ? (AGG) : (IN);                                       \
            __syncthreads();                                                             \
            _Pragma("unroll") for (int j = 0; j < 4; j++) {                              \
                int idx = tid + j * TPB;                                                 \
                ((float4*)Wsm)[idx] = ((const float4*)W)[idx];                           \
            }                                                                            \
            _Pragma("unroll") for (int j = 0; j < 4; j++) {                              \
                int idx = tid + j * TPB;                                                 \
                int r = idx >> 4, c4 = (idx & 15) * 4;                                   \
                int gr = row0 + r;                                                       \
                float4 v = make_float4(0.f, 0.f, 0.f, 0.f);                              \
                if (gr < N_NODES)                                                        \
                    v = ((const float4*)((SP) + (long long)gr * D))[idx & 15];           \
                if (pass) { float iv = invs[r]; v.x*=iv; v.y*=iv; v.z*=iv; v.w*=iv; }    \
                At[r][c4]=v.x; At[r][c4+1]=v.y; At[r][c4+2]=v.z; At[r][c4+3]=v.w;        \
            }                                                                            \
            __syncthreads();                                                             \
            _Pragma("unroll 8") for (int k = 0; k < D; k++) {                            \
                float4 w = *(const float4*)&Wsm[k * D + tc * 4];                         \
                _Pragma("unroll") for (int i = 0; i < 4; i++) {                          \
                    float a = At[tr * 4 + i][k];                                         \
                    acc[i][0] += a * w.x; acc[i][1] += a * w.y;                          \
                    acc[i][2] += a * w.z; acc[i][3] += a * w.w;                          \
                }                                                                        \
            }                                                                            \
        }                                                                                \
        float4 bv = ((const float4*)(BIAS))[tc];                                         \
        _Pragma("unroll") for (int i = 0; i < 4; i++) {                                  \
            int gr = row0 + tr * 4 + i;                                                  \
            if (gr < N_NODES) {                                                          \
                float4 o;                                                                \
                o.x = acc[i][0] + bv.x; o.y = acc[i][1] + bv.y;                          \
                o.z = acc[i][2] + bv.z; o.w = acc[i][3] + bv.w;                          \
                if (RELU) { o.x=fmaxf(o.x,0.f); o.y=fmaxf(o.y,0.f);                      \
                            o.z=fmaxf(o.z,0.f); o.w=fmaxf(o.w,0.f); }                    \
                ((float4*)((OUT) + (long long)gr * D))[tc] = o;                          \
            }                                                                            \
        }                                                                                \
        __syncthreads();                                                                 \
    }

    // ---- phase C: layer 0 GEMM -> g_h (relu) ----
    SAGE_LAYER(x, g_agg0, W_self0, W_neigh0, b0, g_h, true)
    grid_bar();

    // ---- phase D: scatter layer 1 ----
    for (int e = gtid; e < N_EDGES; e += gstride) {
        int s, dn;
        if (is64) {
            s  = (int)((const long long*)srcp)[e];
            dn = (int)((const long long*)dstp)[e];
        } else {
            s  = ((const int*)srcp)[e];
            dn = ((const int*)dstp)[e];
        }
        const float4* fs = (const float4*)(g_h + (long long)s * D);
        float* op = g_agg1 + (long long)dn * D;
#pragma unroll
        for (int j = 0; j < 16; j++) red_add_v4(op + j * 4, __ldg(fs + j));
    }
    grid_bar();

    // ---- phase E: layer 1 GEMM -> out (no relu) ----
    SAGE_LAYER(g_h, g_agg1, W_self1, W_neigh1, b1, outp, false)
}

// ---------------- launch: ONE kernel = ONE graph node ----------------
extern "C" void kernel_launch(void* const* d_in, const int* in_sizes, int n_in,
                              void* d_out, int out_size) {
    const float* x        = (const float*)d_in[0];
    const void*  src      = d_in[1];
    const void*  dst      = d_in[2];
    const float* W_self0  = (const float*)d_in[3];
    const float* W_neigh0 = (const float*)d_in[4];
    const float* b0       = (const float*)d_in[5];
    const float* W_self1  = (const float*)d_in[6];
    const float* W_neigh1 = (const float*)d_in[7];
    const float* b1       = (const float*)d_in[8];
    float* outp = (float*)d_out;

    sage_fused_kernel<<<GRID, TPB>>>(x, src, dst,
                                     W_self0, W_neigh0, b0,
                                     W_self1, W_neigh1, b1, outp);
}

// round 3
// speedup vs baseline: 2.3593x; 2.3593x over previous
#include <cuda_runtime.h>

#define N_NODES 50000
#define N_EDGES 800000
#define D 64
#define GRID 592          // 148 SMs x 4 blocks/SM (<= one wave, also on 152-SM GB300)
#define TPB 256

// ---------------- scratch (static device globals; no allocation) ----------------
__device__ float g_deg[N_NODES];
__device__ float g_agg0[N_NODES * D];
__device__ float g_agg1[N_NODES * D];
__device__ float g_h[N_NODES * D];

// barrier state: monotonic, never reset (safe across graph replays)
__device__ unsigned g_cnt = 0;
__device__ unsigned g_gen = 0;

// ---------------- helpers ----------------
__device__ __forceinline__ void red_add_v4(float* p, float4 v) {
    asm volatile("red.global.add.v4.f32 [%0], {%1,%2,%3,%4};"
                 :: "l"(p), "f"(v.x), "f"(v.y), "f"(v.z), "f"(v.w) : "memory");
}
__device__ __forceinline__ void red_add_f32(float* p, float v) {
    asm volatile("red.global.add.f32 [%0], %1;" :: "l"(p), "f"(v) : "memory");
}

// software grid barrier (all GRID blocks co-resident; monotonic counters)
__device__ __forceinline__ void grid_bar() {
    __syncthreads();
    if (threadIdx.x == 0) {
        __threadfence();
        unsigned my = atomicAdd(&g_cnt, 1u) + 1u;
        unsigned need = (my + GRID - 1u) / GRID;      // barrier round of this arrival
        if ((my % GRID) == 0u) atomicAdd(&g_gen, 1u); // last arrival releases round
        while (*((volatile unsigned*)&g_gen) < need) {}
        __threadfence();
    }
    __syncthreads();
}

// ---------------- fused persistent kernel ----------------
__global__ void __launch_bounds__(TPB, 4)
sage_fused_kernel(const float* __restrict__ x,
                  const void* __restrict__ srcp,
                  const void* __restrict__ dstp,
                  const float* __restrict__ W_self0, const float* __restrict__ W_neigh0,
                  const float* __restrict__ b0,
                  const float* __restrict__ W_self1, const float* __restrict__ W_neigh1,
                  const float* __restrict__ b1,
                  float* __restrict__ outp) {
    const int tid = threadIdx.x;
    const int bid = blockIdx.x;
    const int gtid = bid * TPB + tid;
    const int gstride = GRID * TPB;

    __shared__ float Wsm[D * D];     // 16 KB
    __shared__ float At[D][65];      // ~16.6 KB
    __shared__ float invs[D];
    __shared__ int s_any;

    // ---- index dtype detection (every block computes identically) ----
    if (tid == 0) s_any = 0;
    __syncthreads();
    {
        int any = 0;
        const int* si = (const int*)srcp;
        for (int i = tid; i < 2048; i += TPB) any |= si[2 * i + 1];
        if (any) atomicOr(&s_any, 1);
    }
    __syncthreads();
    const bool is64 = (s_any == 0);  // high words all zero -> int64 little-endian

    // scatter lane mapping: half-warp (16 lanes) per edge, warp does 2 edges/iter
    const int lane = tid & 31;
    const int half = lane >> 4;          // 0 or 1
    const int l16  = lane & 15;          // float4 slot within the 64-float row
    const int gwarp = gtid >> 5;
    const int nwarps = gstride >> 5;

    // ---- phase A: zero scratch ----
    {
        float4 z = make_float4(0.f, 0.f, 0.f, 0.f);
        float4* pd = (float4*)g_deg;
        for (int j = gtid; j < N_NODES / 4; j += gstride) pd[j] = z;
        float4* p0 = (float4*)g_agg0;
        float4* p1 = (float4*)g_agg1;
        for (int j = gtid; j < N_NODES * D / 4; j += gstride) { p0[j] = z; p1[j] = z; }
    }
    grid_bar();

    // ---- phase B: scatter layer 0 (+degree), coalesced half-warp per edge ----
    for (int e0 = gwarp * 2; e0 < N_EDGES; e0 += nwarps * 2) {
        int e = e0 + half;               // N_EDGES even -> always in range
        int s, dn;
        if (is64) {
            s  = (int)((const long long*)srcp)[e];
            dn = (int)((const long long*)dstp)[e];
        } else {
            s  = ((const int*)srcp)[e];
            dn = ((const int*)dstp)[e];
        }
        if (l16 == 0) red_add_f32(&g_deg[dn], 1.0f);
        float4 v = __ldg((const float4*)(x + (long long)s * D) + l16);
        red_add_v4(g_agg0 + (long long)dn * D + l16 * 4, v);
    }
    grid_bar();

    // ---- GEMM phase macro: out = [relu](in@Wself + (agg*inv)@Wneigh + b) ----
    const int tc = tid & 15;    // col group: cols 4*tc..4*tc+3
    const int tr = tid >> 4;    // 0..15 : rows tr*4..tr*4+3
#define SAGE_LAYER(IN, AGG, WSELF, WNEIGH, BIAS, OUT, RELU)                              \
    for (int t = bid; t < (N_NODES + D - 1) / D; t += GRID) {                            \
        const int row0 = t * D;                                                          \
        float acc[4][4];                                                                 \
        _Pragma("unroll") for (int i = 0; i < 4; i++)                                    \
            _Pragma("unroll") for (int j = 0; j < 4; j++) acc[i][j] = 0.f;               \
        if (tid < D) {                                                                   \
            int r = row0 + tid;                                                          \
            float dg = (r < N_NODES) ? g_deg[r] : 1.0f;                                  \
            invs[tid] = 1.0f / fmaxf(dg, 1.0f);                                          \
        }                                                                                \
        _Pragma("unroll 2") for (int pass = 0; pass < 2; pass++) {                       \
            const float* W  = pass ? (WNEIGH) : (WSELF);                                 \
            const float* SP = pass ? (AGG) : (IN);                                       \
            __syncthreads();                                                             \
            _Pragma("unroll") for (int j = 0; j < 4; j++) {                              \
                int idx = tid + j * TPB;                                                 \
                ((float4*)Wsm)[idx] = ((const float4*)W)[idx];                           \
            }                                                                            \
            _Pragma("unroll") for (int j = 0; j < 4; j++) {                              \
                int idx = tid + j * TPB;                                                 \
                int r = idx >> 4, c4 = (idx & 15) * 4;                                   \
                int gr = row0 + r;                                                       \
                float4 v = make_float4(0.f, 0.f, 0.f, 0.f);                              \
                if (gr < N_NODES)                                                        \
                    v = ((const float4*)((SP) + (long long)gr * D))[idx & 15];           \
                if (pass) { float iv = invs[r]; v.x*=iv; v.y*=iv; v.z*=iv; v.w*=iv; }    \
                At[r][c4]=v.x; At[r][c4+1]=v.y; At[r][c4+2]=v.z; At[r][c4+3]=v.w;        \
            }                                                                            \
            __syncthreads();                                                             \
            _Pragma("unroll 8") for (int k = 0; k < D; k++) {                            \
                float4 w = *(const float4*)&Wsm[k * D + tc * 4];                         \
                _Pragma("unroll") for (int i = 0; i < 4; i++) {                          \
                    float a = At[tr * 4 + i][k];                                         \
                    acc[i][0] += a * w.x; acc[i][1] += a * w.y;                          \
                    acc[i][2] += a * w.z; acc[i][3] += a * w.w;                          \
                }                                                                        \
            }                                                                            \
        }                                                                                \
        float4 bv = ((const float4*)(BIAS))[tc];                                         \
        _Pragma("unroll") for (int i = 0; i < 4; i++) {                                  \
            int gr = row0 + tr * 4 + i;                                                  \
            if (gr < N_NODES) {                                                          \
                float4 o;                                                                \
                o.x = acc[i][0] + bv.x; o.y = acc[i][1] + bv.y;                          \
                o.z = acc[i][2] + bv.z; o.w = acc[i][3] + bv.w;                          \
                if (RELU) { o.x=fmaxf(o.x,0.f); o.y=fmaxf(o.y,0.f);                      \
                            o.z=fmaxf(o.z,0.f); o.w=fmaxf(o.w,0.f); }                    \
                ((float4*)((OUT) + (long long)gr * D))[tc] = o;                          \
            }                                                                            \
        }                                                                                \
        __syncthreads();                                                                 \
    }

    // ---- phase C: layer 0 GEMM -> g_h (relu) ----
    SAGE_LAYER(x, g_agg0, W_self0, W_neigh0, b0, g_h, true)
    grid_bar();

    // ---- phase D: scatter layer 1, coalesced half-warp per edge ----
    for (int e0 = gwarp * 2; e0 < N_EDGES; e0 += nwarps * 2) {
        int e = e0 + half;
        int s, dn;
        if (is64) {
            s  = (int)((const long long*)srcp)[e];
            dn = (int)((const long long*)dstp)[e];
        } else {
            s  = ((const int*)srcp)[e];
            dn = ((const int*)dstp)[e];
        }
        float4 v = __ldg((const float4*)(g_h + (long long)s * D) + l16);
        red_add_v4(g_agg1 + (long long)dn * D + l16 * 4, v);
    }
    grid_bar();

    // ---- phase E: layer 1 GEMM -> out (no relu) ----
    SAGE_LAYER(g_h, g_agg1, W_self1, W_neigh1, b1, outp, false)
}

// ---------------- launch: ONE kernel = ONE graph node ----------------
extern "C" void kernel_launch(void* const* d_in, const int* in_sizes, int n_in,
                              void* d_out, int out_size) {
    const float* x        = (const float*)d_in[0];
    const void*  src      = d_in[1];
    const void*  dst      = d_in[2];
    const float* W_self0  = (const float*)d_in[3];
    const float* W_neigh0 = (const float*)d_in[4];
    const float* b0       = (const float*)d_in[5];
    const float* W_self1  = (const float*)d_in[6];
    const float* W_neigh1 = (const float*)d_in[7];
    const float* b1       = (const float*)d_in[8];
    float* outp = (float*)d_out;

    sage_fused_kernel<<<GRID, TPB>>>(x, src, dst,
                                     W_self0, W_neigh0, b0,
                                     W_self1, W_neigh1, b1, outp);
}

// round 4
// speedup vs baseline: 2.3924x; 1.0140x over previous
#include <cuda_runtime.h>

#define N_NODES 50000
#define N_EDGES 800000
#define D 64
#define GRID 592                         // 148 SMs x 4 blocks/SM (one wave incl. 152-SM GB300)
#define TPB 256
#define NT ((N_NODES + 31) / 32)         // 1563 tiles of 32 rows
#define CH ((N_NODES + GRID - 1) / GRID) // 85 nodes per block chunk

// ---------------- scratch (static device globals; no allocation) ----------------
__device__ int   g_degcnt[N_NODES];
__device__ int   g_cursor[N_NODES];
__device__ int   g_rs[N_NODES + 1];      // CSR row starts
__device__ int   g_csr[N_EDGES];         // CSR column (src) indices
__device__ int   g_bsum[GRID];
__device__ int   g_boff[GRID];
__device__ float g_h[N_NODES * D];

// barrier state: monotonic, never reset (safe across graph replays)
__device__ unsigned g_bcnt = 0;
__device__ unsigned g_bgen = 0;

__device__ __forceinline__ void grid_bar() {
    __syncthreads();
    if (threadIdx.x == 0) {
        __threadfence();
        unsigned my = atomicAdd(&g_bcnt, 1u) + 1u;
        unsigned need = (my + GRID - 1u) / GRID;
        if ((my % GRID) == 0u) atomicAdd(&g_bgen, 1u);
        while (*((volatile unsigned*)&g_bgen) < need) {}
        __threadfence();
    }
    __syncthreads();
}

__device__ __forceinline__ int load_idx(const void* p, int e, bool is64) {
    return is64 ? (int)((const long long*)p)[e] : ((const int*)p)[e];
}

// ---------------- fused persistent kernel ----------------
__global__ void __launch_bounds__(TPB, 4)
sage_fused_kernel(const float* __restrict__ x,
                  const void* __restrict__ srcp,
                  const void* __restrict__ dstp,
                  const float* __restrict__ W_self0, const float* __restrict__ W_neigh0,
                  const float* __restrict__ b0,
                  const float* __restrict__ W_self1, const float* __restrict__ W_neigh1,
                  const float* __restrict__ b1,
                  float* __restrict__ outp) {
    const int tid = threadIdx.x;
    const int bid = blockIdx.x;
    const int gtid = bid * TPB + tid;
    const int gstride = GRID * TPB;

    __shared__ float Wsm[2][D * D];   // 32 KB: both weight matrices of current layer
    __shared__ float At[32][65];      // 8.3 KB padded input tile
    __shared__ int   sscan[TPB];      // scan/reduce scratch

    // ---- index dtype detection (every block computes identically) ----
    if (tid == 0) sscan[0] = 0;
    __syncthreads();
    {
        int any = 0;
        const int* si = (const int*)srcp;
        for (int i = tid; i < 2048; i += TPB) any |= si[2 * i + 1];
        if (any) atomicOr(&sscan[0], 1);
    }
    __syncthreads();
    const bool is64 = (sscan[0] == 0);   // high words all zero -> int64 little-endian

    // ---- phase A: zero counters ----
    for (int j = gtid; j < N_NODES; j += gstride) { g_degcnt[j] = 0; g_cursor[j] = 0; }
    grid_bar();

    // ---- phase B: degree histogram ----
    for (int e = gtid; e < N_EDGES; e += gstride)
        atomicAdd(&g_degcnt[load_idx(dstp, e, is64)], 1);
    grid_bar();

    // ---- phase C: per-block chunk sums ----
    {
        int n0 = bid * CH;
        int n = N_NODES - n0; if (n > CH) n = CH; if (n < 0) n = 0;
        int v = (tid < n) ? g_degcnt[n0 + tid] : 0;
        sscan[tid] = v; __syncthreads();
        for (int off = TPB / 2; off > 0; off >>= 1) {
            if (tid < off) sscan[tid] += sscan[tid + off];
            __syncthreads();
        }
        if (tid == 0) g_bsum[bid] = sscan[0];
    }
    grid_bar();

    // ---- phase D: block 0 scans the 592 chunk sums ----
    if (bid == 0) {
        int v[3]; int mysum = 0;
#pragma unroll
        for (int k = 0; k < 3; k++) {
            int idx = tid * 3 + k;
            v[k] = (idx < GRID) ? g_bsum[idx] : 0;
            mysum += v[k];
        }
        sscan[tid] = mysum; __syncthreads();
        for (int off = 1; off < TPB; off <<= 1) {
            int t = (tid >= off) ? sscan[tid - off] : 0;
            __syncthreads();
            sscan[tid] += t;
            __syncthreads();
        }
        int run = sscan[tid] - mysum;   // exclusive prefix of thread sums
#pragma unroll
        for (int k = 0; k < 3; k++) {
            int idx = tid * 3 + k;
            if (idx < GRID) g_boff[idx] = run;
            run += v[k];
        }
    }
    grid_bar();

    // ---- phase E: per-chunk exclusive scan -> row starts ----
    {
        int n0 = bid * CH;
        int n = N_NODES - n0; if (n > CH) n = CH; if (n < 0) n = 0;
        int v = (tid < n) ? g_degcnt[n0 + tid] : 0;
        sscan[tid] = v; __syncthreads();
        for (int off = 1; off < TPB; off <<= 1) {
            int t = (tid >= off) ? sscan[tid - off] : 0;
            __syncthreads();
            sscan[tid] += t;
            __syncthreads();
        }
        if (tid < n) g_rs[n0 + tid] = g_boff[bid] + sscan[tid] - v;
        if (bid == 0 && tid == 0) g_rs[N_NODES] = N_EDGES;
    }
    grid_bar();

    // ---- phase F: fill CSR ----
    for (int e = gtid; e < N_EDGES; e += gstride) {
        int dn = load_idx(dstp, e, is64);
        int s  = load_idx(srcp, e, is64);
        int pos = atomicAdd(&g_cursor[dn], 1);
        g_csr[g_rs[dn] + pos] = s;
    }
    grid_bar();

    // ---- fused layer: out = [relu](in@Wself + mean_gather(in)@Wneigh + b) ----
    const int tc = tid & 15;     // col group: cols 4*tc..4*tc+3 (also lane-in-halfwarp)
    const int tr = tid >> 4;     // 0..15: rows tr*2, tr*2+1 (also halfwarp id)

#define SAGE_LAYER(IN, WSELF, WNEIGH, BIAS, OUT, RELU)                                    \
    {                                                                                     \
        _Pragma("unroll") for (int j = 0; j < 4; j++) {                                   \
            int idx = tid + j * TPB;                                                      \
            ((float4*)Wsm[0])[idx] = ((const float4*)(WSELF))[idx];                       \
            ((float4*)Wsm[1])[idx] = ((const float4*)(WNEIGH))[idx];                      \
        }                                                                                 \
        for (int t = bid; t < NT; t += GRID) {                                            \
            const int row0 = t * 32;                                                      \
            float acc[2][4];                                                              \
            _Pragma("unroll") for (int i = 0; i < 2; i++)                                 \
                _Pragma("unroll") for (int j = 0; j < 4; j++) acc[i][j] = 0.f;            \
            /* pass 0: self features */                                                   \
            __syncthreads();                                                              \
            _Pragma("unroll") for (int j = 0; j < 2; j++) {                               \
                int idx = tid + j * TPB;                                                  \
                int r = idx >> 4, c = idx & 15;                                           \
                int gr = row0 + r;                                                        \
                float4 v = make_float4(0.f, 0.f, 0.f, 0.f);                               \
                if (gr < N_NODES) v = ((const float4*)((IN) + (long long)gr * D))[c];     \
                At[r][c*4] = v.x; At[r][c*4+1] = v.y;                                     \
                At[r][c*4+2] = v.z; At[r][c*4+3] = v.w;                                   \
            }                                                                             \
            __syncthreads();                                                              \
            _Pragma("unroll 4") for (int k = 0; k < D; k++) {                             \
                float4 w = *(const float4*)&Wsm[0][k * D + tc * 4];                       \
                float a0 = At[tr*2][k], a1 = At[tr*2+1][k];                               \
                acc[0][0] += a0*w.x; acc[0][1] += a0*w.y;                                 \
                acc[0][2] += a0*w.z; acc[0][3] += a0*w.w;                                 \
                acc[1][0] += a1*w.x; acc[1][1] += a1*w.y;                                 \
                acc[1][2] += a1*w.z; acc[1][3] += a1*w.w;                                 \
            }                                                                             \
            __syncthreads();                                                              \
            /* pass 1: gather mean of neighbors into At (halfwarp tr owns 2 rows) */      \
            _Pragma("unroll") for (int i = 0; i < 2; i++) {                               \
                int r = tr * 2 + i;                                                       \
                int gr = row0 + r;                                                        \
                float4 a0 = make_float4(0,0,0,0), a1 = a0, a2 = a0, a3 = a0;              \
                float iv = 0.f;                                                           \
                if (gr < N_NODES) {                                                       \
                    int beg = g_rs[gr], end = g_rs[gr + 1];                               \
                    int e = beg;                                                          \
                    for (; e + 3 < end; e += 4) {                                         \
                        int s0 = g_csr[e],   s1 = g_csr[e+1];                             \
                        int s2 = g_csr[e+2], s3 = g_csr[e+3];                             \
                        float4 v0 = __ldg((const float4*)((IN)+(long long)s0*D)+tc);      \
                        float4 v1 = __ldg((const float4*)((IN)+(long long)s1*D)+tc);      \
                        float4 v2 = __ldg((const float4*)((IN)+(long long)s2*D)+tc);      \
                        float4 v3 = __ldg((const float4*)((IN)+(long long)s3*D)+tc);      \
                        a0.x+=v0.x; a0.y+=v0.y; a0.z+=v0.z; a0.w+=v0.w;                   \
                        a1.x+=v1.x; a1.y+=v1.y; a1.z+=v1.z; a1.w+=v1.w;                   \
                        a2.x+=v2.x; a2.y+=v2.y; a2.z+=v2.z; a2.w+=v2.w;                   \
                        a3.x+=v3.x; a3.y+=v3.y; a3.z+=v3.z; a3.w+=v3.w;                   \
                    }                                                                     \
                    for (; e < end; e++) {                                                \
                        int s0 = g_csr[e];                                                \
                        float4 v0 = __ldg((const float4*)((IN)+(long long)s0*D)+tc);      \
                        a0.x+=v0.x; a0.y+=v0.y; a0.z+=v0.z; a0.w+=v0.w;                   \
                    }                                                                     \
                    iv = 1.0f / fmaxf((float)(end - beg), 1.0f);                          \
                }                                                                         \
                float4 s;                                                                 \
                s.x = ((a0.x+a1.x)+(a2.x+a3.x)) * iv;                                     \
                s.y = ((a0.y+a1.y)+(a2.y+a3.y)) * iv;                                     \
                s.z = ((a0.z+a1.z)+(a2.z+a3.z)) * iv;                                     \
                s.w = ((a0.w+a1.w)+(a2.w+a3.w)) * iv;                                     \
                At[r][tc*4] = s.x; At[r][tc*4+1] = s.y;                                   \
                At[r][tc*4+2] = s.z; At[r][tc*4+3] = s.w;                                 \
            }                                                                             \
            __syncthreads();                                                              \
            _Pragma("unroll 4") for (int k = 0; k < D; k++) {                             \
                float4 w = *(const float4*)&Wsm[1][k * D + tc * 4];                       \
                float a0 = At[tr*2][k], a1 = At[tr*2+1][k];                               \
                acc[0][0] += a0*w.x; acc[0][1] += a0*w.y;                                 \
                acc[0][2] += a0*w.z; acc[0][3] += a0*w.w;                                 \
                acc[1][0] += a1*w.x; acc[1][1] += a1*w.y;                                 \
                acc[1][2] += a1*w.z; acc[1][3] += a1*w.w;                                 \
            }                                                                             \
            float4 bv = ((const float4*)(BIAS))[tc];                                      \
            _Pragma("unroll") for (int i = 0; i < 2; i++) {                               \
                int gr = row0 + tr * 2 + i;                                               \
                if (gr < N_NODES) {                                                       \
                    float4 o;                                                             \
                    o.x = acc[i][0] + bv.x; o.y = acc[i][1] + bv.y;                       \
                    o.z = acc[i][2] + bv.z; o.w = acc[i][3] + bv.w;                       \
                    if (RELU) { o.x=fmaxf(o.x,0.f); o.y=fmaxf(o.y,0.f);                   \
                                o.z=fmaxf(o.z,0.f); o.w=fmaxf(o.w,0.f); }                 \
                    ((float4*)((OUT) + (long long)gr * D))[tc] = o;                       \
                }                                                                         \
            }                                                                             \
        }                                                                                 \
    }

    // ---- phase G: layer 0 -> g_h (relu) ----
    SAGE_LAYER(x, W_self0, W_neigh0, b0, g_h, true)
    grid_bar();

    // ---- phase H: layer 1 -> out (no relu) ----
    SAGE_LAYER(g_h, W_self1, W_neigh1, b1, outp, false)
}

// ---------------- launch: ONE kernel = ONE graph node ----------------
extern "C" void kernel_launch(void* const* d_in, const int* in_sizes, int n_in,
                              void* d_out, int out_size) {
    const float* x        = (const float*)d_in[0];
    const void*  src      = d_in[1];
    const void*  dst      = d_in[2];
    const float* W_self0  = (const float*)d_in[3];
    const float* W_neigh0 = (const float*)d_in[4];
    const float* b0       = (const float*)d_in[5];
    const float* W_self1  = (const float*)d_in[6];
    const float* W_neigh1 = (const float*)d_in[7];
    const float* b1       = (const float*)d_in[8];
    float* outp = (float*)d_out;

    sage_fused_kernel<<<GRID, TPB>>>(x, src, dst,
                                     W_self0, W_neigh0, b0,
                                     W_self1, W_neigh1, b1, outp);
}

// round 5
// speedup vs baseline: 2.4276x; 1.0147x over previous
#include <cuda_runtime.h>

#define N_NODES 50000
#define N_EDGES 800000
#define D 64
#define GRID 592                         // 148 SMs x 4 blocks/SM (one wave incl. 152-SM GB300)
#define TPB 256
#define NT ((N_NODES + 31) / 32)         // 1563 tiles of 32 rows
#define CH ((N_NODES + GRID - 1) / GRID) // 85 nodes per block chunk
#define SIDX_CAP 1024                    // smem CSR stage capacity (avg tile = 512 edges)

// ---------------- scratch (static device globals; no allocation) ----------------
__device__ int   g_degcnt[N_NODES];
__device__ int   g_cursor[N_NODES];
__device__ int   g_rs[N_NODES + 1];      // CSR row starts
__device__ int   g_csr[N_EDGES];         // CSR column (src) indices
__device__ int   g_bsum[GRID];
__device__ int   g_boff[GRID];
__device__ int   g_tile[2];              // dynamic tile counters (one per layer)
__device__ float g_h[N_NODES * D];

// barrier state: monotonic, never reset (safe across graph replays)
__device__ unsigned g_bcnt = 0;
__device__ unsigned g_bgen = 0;

__device__ __forceinline__ void grid_bar() {
    __syncthreads();
    if (threadIdx.x == 0) {
        __threadfence();
        unsigned my = atomicAdd(&g_bcnt, 1u) + 1u;
        unsigned need = (my + GRID - 1u) / GRID;
        if ((my % GRID) == 0u) atomicAdd(&g_bgen, 1u);
        while (*((volatile unsigned*)&g_bgen) < need) {}
        __threadfence();
    }
    __syncthreads();
}

__device__ __forceinline__ int load_idx(const void* p, int e, bool is64) {
    return is64 ? (int)((const long long*)p)[e] : ((const int*)p)[e];
}

// ---------------- fused persistent kernel ----------------
__global__ void __launch_bounds__(TPB, 4)
sage_fused_kernel(const float* __restrict__ x,
                  const void* __restrict__ srcp,
                  const void* __restrict__ dstp,
                  const float* __restrict__ W_self0, const float* __restrict__ W_neigh0,
                  const float* __restrict__ b0,
                  const float* __restrict__ W_self1, const float* __restrict__ W_neigh1,
                  const float* __restrict__ b1,
                  float* __restrict__ outp) {
    const int tid = threadIdx.x;
    const int bid = blockIdx.x;
    const int gtid = bid * TPB + tid;
    const int gstride = GRID * TPB;

    __shared__ float Wsm[2][D * D];   // 32 KB: both weight matrices of current layer
    __shared__ float At[32][65];      // 8.3 KB padded input tile
    __shared__ int   sidx[SIDX_CAP];  // 4 KB: staged CSR indices (aliased as scan scratch)
    __shared__ int   rb[33];          // tile row bounds
    __shared__ int   s_t;             // dynamic tile id
    int* sscan = sidx;                // alias: scan scratch only used in CSR-build phases

    // ---- index dtype detection (every block computes identically) ----
    if (tid == 0) sscan[0] = 0;
    __syncthreads();
    {
        int any = 0;
        const int* si = (const int*)srcp;
        for (int i = tid; i < 2048; i += TPB) any |= si[2 * i + 1];
        if (any) atomicOr(&sscan[0], 1);
    }
    __syncthreads();
    const bool is64 = (sscan[0] == 0);   // high words all zero -> int64 little-endian

    // ---- phase A: zero counters ----
    for (int j = gtid; j < N_NODES; j += gstride) { g_degcnt[j] = 0; g_cursor[j] = 0; }
    if (gtid < 2) g_tile[gtid] = 0;
    grid_bar();

    // ---- phase B: degree histogram ----
    for (int e = gtid; e < N_EDGES; e += gstride)
        atomicAdd(&g_degcnt[load_idx(dstp, e, is64)], 1);
    grid_bar();

    // ---- phase C: per-block chunk sums ----
    {
        int n0 = bid * CH;
        int n = N_NODES - n0; if (n > CH) n = CH; if (n < 0) n = 0;
        int v = (tid < n) ? g_degcnt[n0 + tid] : 0;
        sscan[tid] = v; __syncthreads();
        for (int off = TPB / 2; off > 0; off >>= 1) {
            if (tid < off) sscan[tid] += sscan[tid + off];
            __syncthreads();
        }
        if (tid == 0) g_bsum[bid] = sscan[0];
    }
    grid_bar();

    // ---- phase D: block 0 scans the 592 chunk sums ----
    if (bid == 0) {
        int v[3]; int mysum = 0;
#pragma unroll
        for (int k = 0; k < 3; k++) {
            int idx = tid * 3 + k;
            v[k] = (idx < GRID) ? g_bsum[idx] : 0;
            mysum += v[k];
        }
        sscan[tid] = mysum; __syncthreads();
        for (int off = 1; off < TPB; off <<= 1) {
            int t = (tid >= off) ? sscan[tid - off] : 0;
            __syncthreads();
            sscan[tid] += t;
            __syncthreads();
        }
        int run = sscan[tid] - mysum;   // exclusive prefix of thread sums
#pragma unroll
        for (int k = 0; k < 3; k++) {
            int idx = tid * 3 + k;
            if (idx < GRID) g_boff[idx] = run;
            run += v[k];
        }
    }
    grid_bar();

    // ---- phase E: per-chunk exclusive scan -> row starts ----
    {
        int n0 = bid * CH;
        int n = N_NODES - n0; if (n > CH) n = CH; if (n < 0) n = 0;
        int v = (tid < n) ? g_degcnt[n0 + tid] : 0;
        sscan[tid] = v; __syncthreads();
        for (int off = 1; off < TPB; off <<= 1) {
            int t = (tid >= off) ? sscan[tid - off] : 0;
            __syncthreads();
            sscan[tid] += t;
            __syncthreads();
        }
        if (tid < n) g_rs[n0 + tid] = g_boff[bid] + sscan[tid] - v;
        if (bid == 0 && tid == 0) g_rs[N_NODES] = N_EDGES;
    }
    grid_bar();

    // ---- phase F: fill CSR ----
    for (int e = gtid; e < N_EDGES; e += gstride) {
        int dn = load_idx(dstp, e, is64);
        int s  = load_idx(srcp, e, is64);
        int pos = atomicAdd(&g_cursor[dn], 1);
        g_csr[g_rs[dn] + pos] = s;
    }
    grid_bar();

    // ---- fused layer: out = [relu](in@Wself + mean_gather(in)@Wneigh + b) ----
    const int tc = tid & 15;     // col group: cols 4*tc..4*tc+3 (lane-in-halfwarp)
    const int tr = tid >> 4;     // 0..15: halfwarp id, owns rows tr*2, tr*2+1

#define GATHER_ACCUM(IDX_EXPR)                                                            \
    {                                                                                     \
        int e = lbeg;                                                                     \
        for (; e + 3 < lend; e += 4) {                                                    \
            int s0 = (IDX_EXPR(e));     int s1 = (IDX_EXPR(e + 1));                       \
            int s2 = (IDX_EXPR(e + 2)); int s3 = (IDX_EXPR(e + 3));                       \
            float4 v0 = __ldg((const float4*)(inp + (long long)s0 * D) + tc);             \
            float4 v1 = __ldg((const float4*)(inp + (long long)s1 * D) + tc);             \
            float4 v2 = __ldg((const float4*)(inp + (long long)s2 * D) + tc);             \
            float4 v3 = __ldg((const float4*)(inp + (long long)s3 * D) + tc);             \
            a0.x+=v0.x; a0.y+=v0.y; a0.z+=v0.z; a0.w+=v0.w;                               \
            a1.x+=v1.x; a1.y+=v1.y; a1.z+=v1.z; a1.w+=v1.w;                               \
            a2.x+=v2.x; a2.y+=v2.y; a2.z+=v2.z; a2.w+=v2.w;                               \
            a3.x+=v3.x; a3.y+=v3.y; a3.z+=v3.z; a3.w+=v3.w;                               \
        }                                                                                 \
        for (; e < lend; e++) {                                                           \
            int s0 = (IDX_EXPR(e));                                                       \
            float4 v0 = __ldg((const float4*)(inp + (long long)s0 * D) + tc);             \
            a0.x+=v0.x; a0.y+=v0.y; a0.z+=v0.z; a0.w+=v0.w;                               \
        }                                                                                 \
    }
#define IDX_SMEM(E)  sidx[E]
#define IDX_GMEM(E)  g_csr[ebase + (E)]

#define SAGE_LAYER(IN, WSELF, WNEIGH, BIAS, OUT, RELU, LYR)                               \
    {                                                                                     \
        const float* inp = (IN);                                                          \
        _Pragma("unroll") for (int j = 0; j < 4; j++) {                                   \
            int idx = tid + j * TPB;                                                      \
            ((float4*)Wsm[0])[idx] = ((const float4*)(WSELF))[idx];                       \
            ((float4*)Wsm[1])[idx] = ((const float4*)(WNEIGH))[idx];                      \
        }                                                                                 \
        for (;;) {                                                                        \
            __syncthreads();                                                              \
            if (tid == 0) s_t = atomicAdd(&g_tile[LYR], 1);                               \
            __syncthreads();                                                              \
            const int t = s_t;                                                            \
            if (t >= NT) break;                                                           \
            const int row0 = t * 32;                                                      \
            /* stage row bounds + CSR segment */                                          \
            if (tid < 33) {                                                               \
                int rr = row0 + tid; if (rr > N_NODES) rr = N_NODES;                      \
                rb[tid] = g_rs[rr];                                                       \
            }                                                                             \
            __syncthreads();                                                              \
            const int ebase = rb[0];                                                      \
            const int ecnt  = rb[32] - ebase;                                             \
            const bool fits = (ecnt <= SIDX_CAP);                                         \
            if (fits) for (int j = tid; j < ecnt; j += TPB) sidx[j] = g_csr[ebase + j];   \
            /* self features into At */                                                   \
            _Pragma("unroll") for (int j = 0; j < 2; j++) {                               \
                int idx = tid + j * TPB;                                                  \
                int r = idx >> 4, c = idx & 15;                                           \
                int gr = row0 + r;                                                        \
                float4 v = make_float4(0.f, 0.f, 0.f, 0.f);                               \
                if (gr < N_NODES) v = ((const float4*)(inp + (long long)gr * D))[c];      \
                At[r][c*4] = v.x; At[r][c*4+1] = v.y;                                     \
                At[r][c*4+2] = v.z; At[r][c*4+3] = v.w;                                   \
            }                                                                             \
            __syncthreads();                                                              \
            float acc[2][4];                                                              \
            _Pragma("unroll") for (int i = 0; i < 2; i++)                                 \
                _Pragma("unroll") for (int j = 0; j < 4; j++) acc[i][j] = 0.f;            \
            _Pragma("unroll 4") for (int k = 0; k < D; k++) {                             \
                float4 w = *(const float4*)&Wsm[0][k * D + tc * 4];                       \
                float p0 = At[tr*2][k], p1 = At[tr*2+1][k];                               \
                acc[0][0] += p0*w.x; acc[0][1] += p0*w.y;                                 \
                acc[0][2] += p0*w.z; acc[0][3] += p0*w.w;                                 \
                acc[1][0] += p1*w.x; acc[1][1] += p1*w.y;                                 \
                acc[1][2] += p1*w.z; acc[1][3] += p1*w.w;                                 \
            }                                                                             \
            __syncthreads();                                                              \
            /* gather mean of neighbors into At (halfwarp tr owns 2 rows) */              \
            _Pragma("unroll") for (int i = 0; i < 2; i++) {                               \
                int r = tr * 2 + i;                                                       \
                int gr = row0 + r;                                                        \
                float4 a0 = make_float4(0,0,0,0), a1 = a0, a2 = a0, a3 = a0;              \
                float iv = 0.f;                                                           \
                if (gr < N_NODES) {                                                       \
                    int lbeg = rb[r] - ebase, lend = rb[r + 1] - ebase;                   \
                    if (fits) GATHER_ACCUM(IDX_SMEM)                                      \
                    else      GATHER_ACCUM(IDX_GMEM)                                      \
                    iv = 1.0f / fmaxf((float)(lend - lbeg), 1.0f);                        \
                }                                                                         \
                float4 s;                                                                 \
                s.x = ((a0.x+a1.x)+(a2.x+a3.x)) * iv;                                     \
                s.y = ((a0.y+a1.y)+(a2.y+a3.y)) * iv;                                     \
                s.z = ((a0.z+a1.z)+(a2.z+a3.z)) * iv;                                     \
                s.w = ((a0.w+a1.w)+(a2.w+a3.w)) * iv;                                     \
                At[r][tc*4] = s.x; At[r][tc*4+1] = s.y;                                   \
                At[r][tc*4+2] = s.z; At[r][tc*4+3] = s.w;                                 \
            }                                                                             \
            __syncthreads();                                                              \
            _Pragma("unroll 4") for (int k = 0; k < D; k++) {                             \
                float4 w = *(const float4*)&Wsm[1][k * D + tc * 4];                       \
                float p0 = At[tr*2][k], p1 = At[tr*2+1][k];                               \
                acc[0][0] += p0*w.x; acc[0][1] += p0*w.y;                                 \
                acc[0][2] += p0*w.z; acc[0][3] += p0*w.w;                                 \
                acc[1][0] += p1*w.x; acc[1][1] += p1*w.y;                                 \
                acc[1][2] += p1*w.z; acc[1][3] += p1*w.w;                                 \
            }                                                                             \
            float4 bv = ((const float4*)(BIAS))[tc];                                      \
            _Pragma("unroll") for (int i = 0; i < 2; i++) {                               \
                int gr = row0 + tr * 2 + i;                                               \
                if (gr < N_NODES) {                                                       \
                    float4 o;                                                             \
                    o.x = acc[i][0] + bv.x; o.y = acc[i][1] + bv.y;                       \
                    o.z = acc[i][2] + bv.z; o.w = acc[i][3] + bv.w;                       \
                    if (RELU) { o.x=fmaxf(o.x,0.f); o.y=fmaxf(o.y,0.f);                   \
                                o.z=fmaxf(o.z,0.f); o.w=fmaxf(o.w,0.f); }                 \
                    ((float4*)((OUT) + (long long)gr * D))[tc] = o;                       \
                }                                                                         \
            }                                                                             \
        }                                                                                 \
    }

    // ---- phase G: layer 0 -> g_h (relu) ----
    SAGE_LAYER(x, W_self0, W_neigh0, b0, g_h, true, 0)
    grid_bar();

    // ---- phase H: layer 1 -> out (no relu) ----
    SAGE_LAYER(g_h, W_self1, W_neigh1, b1, outp, false, 1)
}

// ---------------- launch: ONE kernel = ONE graph node ----------------
extern "C" void kernel_launch(void* const* d_in, const int* in_sizes, int n_in,
                              void* d_out, int out_size) {
    const float* x        = (const float*)d_in[0];
    const void*  src      = d_in[1];
    const void*  dst      = d_in[2];
    const float* W_self0  = (const float*)d_in[3];
    const float* W_neigh0 = (const float*)d_in[4];
    const float* b0       = (const float*)d_in[5];
    const float* W_self1  = (const float*)d_in[6];
    const float* W_neigh1 = (const float*)d_in[7];
    const float* b1       = (const float*)d_in[8];
    float* outp = (float*)d_out;

    sage_fused_kernel<<<GRID, TPB>>>(x, src, dst,
                                     W_self0, W_neigh0, b0,
                                     W_self1, W_neigh1, b1, outp);
}